// round 13
// baseline (speedup 1.0000x reference)
#include <cuda_runtime.h>
#include <cuda_fp16.h>
#include <cstdint>

#define TC      16
#define HID     128
#define PCH     48
#define THREADS 256
#define NROWT   8192                // row-tiles: 32 batches * 256 rows

#define GS_STR  264                 // floats per Gs row, interior at col 4 (pix 0..255)
#define AT_STR  264                 // halfs per AsT row
#define W1_STR  56
#define W2_STR  136
#define GO_STR  260                 // floats per Gout row (bank-conflict-free)

#define OFF_GS   0
#define OFF_AST  (16*3*GS_STR*4)                  // 50688
#define OFF_WH1  (OFF_AST + PCH*AT_STR*2)         // 76032
#define OFF_WH2  (OFF_WH1 + HID*W1_STR*2)         // 90368
#define OFF_GOUT (OFF_WH2 + TC*W2_STR*2)          // 94720
#define SMEM_BYTES (OFF_GOUT + TC*GO_STR*4)       // 111360

// Pre-converted, pre-padded weights (k-permuted w1: k = 16*filter + channel).
// Sobel filter rows (f=1,2) are pre-scaled by 0.125 so the kernel skips the mul.
__device__ __align__(16) half  g_wh1p[HID * W1_STR];
__device__ __align__(16) half  g_wh2p[TC * W2_STR];
__device__ __align__(16) half2 g_b1h2[HID / 2];

__global__ void convert_weights_kernel(const float* __restrict__ w1,
                                       const float* __restrict__ b1,
                                       const float* __restrict__ w2)
{
    int t = threadIdx.x;
    for (int i = t; i < HID * W1_STR; i += THREADS) g_wh1p[i] = __float2half(0.f);
    for (int i = t; i < TC * W2_STR; i += THREADS) g_wh2p[i] = __float2half(0.f);
    __syncthreads();
    for (int i = t; i < HID * PCH; i += THREADS) {
        int o = i / PCH, p = i % PCH;
        int c = p / 3, f = p % 3;                  // src col p = 3c+f
        float scale = (f == 0) ? 1.f : 0.125f;     // fold sobel /8 into weights
        g_wh1p[o * W1_STR + f * 16 + c] = __float2half(w1[i] * scale);
    }
    for (int i = t; i < TC * HID; i += THREADS)
        g_wh2p[(i / HID) * W2_STR + (i % HID)] = __float2half(w2[i]);
    if (t < HID / 2)
        g_b1h2[t] = __floats2half2_rn(b1[2 * t], b1[2 * t + 1]);
}

__device__ __forceinline__ void mma_f16acc(unsigned* d,
    unsigned a0, unsigned a1, unsigned a2, unsigned a3,
    unsigned b0, unsigned b1)
{
    asm volatile(
        "mma.sync.aligned.m16n8k16.row.col.f16.f16.f16.f16 "
        "{%0,%1}, {%2,%3,%4,%5}, {%6,%7}, {%0,%1};\n"
        : "+r"(d[0]), "+r"(d[1])
        : "r"(a0), "r"(a1), "r"(a2), "r"(a3), "r"(b0), "r"(b1));
}

__device__ __forceinline__ void mma_f32acc(float* d,
    unsigned a0, unsigned a1, unsigned a2, unsigned a3,
    unsigned b0, unsigned b1)
{
    asm volatile(
        "mma.sync.aligned.m16n8k16.row.col.f32.f16.f16.f32 "
        "{%0,%1,%2,%3}, {%4,%5,%6,%7}, {%8,%9}, {%0,%1,%2,%3};\n"
        : "+f"(d[0]), "+f"(d[1]), "+f"(d[2]), "+f"(d[3])
        : "r"(a0), "r"(a1), "r"(a2), "r"(a3), "r"(b0), "r"(b1));
}

__device__ __forceinline__ void ldm_x4(unsigned& r0, unsigned& r1,
                                       unsigned& r2, unsigned& r3, uint32_t addr)
{
    asm volatile(
        "ldmatrix.sync.aligned.m8n8.x4.shared.b16 {%0,%1,%2,%3}, [%4];\n"
        : "=r"(r0), "=r"(r1), "=r"(r2), "=r"(r3) : "r"(addr));
}

__device__ __forceinline__ void ldm_x4_trans(unsigned& r0, unsigned& r1,
                                             unsigned& r2, unsigned& r3, uint32_t addr)
{
    asm volatile(
        "ldmatrix.sync.aligned.m8n8.x4.trans.shared.b16 {%0,%1,%2,%3}, [%4];\n"
        : "=r"(r0), "=r"(r1), "=r"(r2), "=r"(r3) : "r"(addr));
}

// relu(a + bias) in one instruction
__device__ __forceinline__ unsigned hfma2_relu_bias(unsigned a, unsigned bias)
{
    unsigned d;
    const unsigned one2 = 0x3C003C00u;
    asm("fma.rn.relu.f16x2 %0, %1, %2, %3;\n" : "=r"(d) : "r"(a), "r"(one2), "r"(bias));
    return d;
}

// full restage: rows h-1, h, h+1 into slots (row mod 3); zero when OOB
__device__ __forceinline__ void full_restage(float* Gs, const float* __restrict__ grid,
                                             int b, int h, int tid)
{
    #pragma unroll
    for (int j = 0; j < 12; j++) {
        int idx   = j * THREADS + tid;       // 0..3071
        int rowid = idx >> 6;                // 0..47
        int c     = rowid / 3;
        int rr    = rowid - c * 3;           // 0..2
        int colq  = idx & 63;
        int r_img = h + rr - 1;
        int slot  = (unsigned)(r_img + 3) % 3u;   // (r_img mod 3), safe for -1
        float4 v  = make_float4(0.f, 0.f, 0.f, 0.f);
        if ((unsigned)r_img < 256u)
            v = *(const float4*)&grid[((((b*TC + c) << 8) + r_img) << 8) + (colq << 2)];
        *(float4*)&Gs[(c*3 + slot)*GS_STR + 4 + (colq << 2)] = v;
    }
}

__global__ __launch_bounds__(THREADS, 2)
void nca_step_kernel(const float* __restrict__ grid,
                     const float* __restrict__ noise,
                     const float* __restrict__ b2,
                     float* __restrict__ out,
                     int ncta)
{
    extern __shared__ __align__(128) char smem_raw[];
    float* Gs   = (float*)(smem_raw + OFF_GS);     // [16][3 slots][264]
    half*  AsT  = (half*)(smem_raw + OFF_AST);     // [48][264] k-major
    half*  Wh1  = (half*)(smem_raw + OFF_WH1);     // [128][56]
    half*  Wh2  = (half*)(smem_raw + OFF_WH2);     // [16][136]
    float* Gout = (float*)(smem_raw + OFF_GOUT);   // [16][260] output stage

    const int tid = threadIdx.x;
    const int cta = blockIdx.x;

    const int base  = NROWT / ncta;
    const int rem   = NROWT % ncta;
    const int start = cta * base + (cta < rem ? cta : rem);
    const int cnt   = base + (cta < rem ? 1 : 0);

    // ---- stage weights once per CTA ----
    {
        const uint4* s1 = (const uint4*)g_wh1p;
        uint4*       d1 = (uint4*)Wh1;
        for (int i = tid; i < (HID*W1_STR)/8; i += THREADS) d1[i] = s1[i];
        const uint4* s2 = (const uint4*)g_wh2p;
        uint4*       d2 = (uint4*)Wh2;
        for (int i = tid; i < (TC*W2_STR)/8; i += THREADS) d2[i] = s2[i];
    }
    // static side-halo columns: always image-OOB -> zero once
    if (tid < 96) {
        int rowid = tid >> 1;
        int side  = tid & 1;
        int c     = rowid / 3;
        int r     = rowid - c * 3;
        Gs[(c*3 + r)*GS_STR + (side ? 260 : 3)] = 0.f;
    }

    // ---- per-thread constants ----
    const int lane = tid & 31;
    const int g    = lane >> 2;
    const int tg   = lane & 3;
    const int m0   = (tid >> 5) << 5;              // 32 pixels per warp

    const uint32_t ast_sm = (uint32_t)__cvta_generic_to_shared(AsT);
    const uint32_t a_row  = (lane & 7) + ((lane >> 4) << 3);
    const uint32_t a_b0   = ast_sm + (uint32_t)((a_row * AT_STR + m0      + (lane & 8)) * 2);
    const uint32_t a_b1   = ast_sm + (uint32_t)((a_row * AT_STR + m0 + 16 + (lane & 8)) * 2);
    const uint32_t brow = (lane & 7) + ((lane >> 4) << 3);
    const uint32_t bkof = (lane & 8);
    const uint32_t b1_base = (uint32_t)__cvta_generic_to_shared(Wh1) + (brow * W1_STR + bkof) * 2;
    const uint32_t b2_base = (uint32_t)__cvta_generic_to_shared(Wh2) + (brow * W2_STR + bkof) * 2;

    float bb_[2][2];
    #pragma unroll
    for (int nt = 0; nt < 2; nt++)
        #pragma unroll
        for (int rr = 0; rr < 2; rr++)
            bb_[nt][rr] = b2[(nt << 3) + 2*tg + rr];

    // perception lane mapping: channel-group base, pixel group
    const int pg    = lane & 7;                    // pixel group 0..7
    const int cgrp  = lane >> 3;                   // 0..3
    const int pxl   = m0 + (pg << 2);              // first of this lane's 4 pixels

    // ---- prologue: full stage of first tile ----
    full_restage(Gs, grid, start >> 8, start & 255, tid);
    __syncthreads();

    for (int i = 0; i < cnt; i++) {
        const int tile = start + i;
        const int b    = tile >> 8;
        const int h    = tile & 255;

        const int s1r = (unsigned)h % 3u;                       // row h
        const int s2r = (s1r + 1 == 3) ? 0 : s1r + 1;           // row h+1
        const int s0r = (s1r == 0) ? 2 : s1r - 1;               // row h-1

        if (h == 0 && i > 0) {                     // batch crossing
            full_restage(Gs, grid, b, 0, tid);
            __syncthreads();
        }

        // ---- perception: WARP-LOCAL (each warp computes its own 32 pixels) ----
        #pragma unroll
        for (int q = 0; q < 4; q++) {
            const int c = q + (cgrp << 2);         // channel 0..15 (bank-safe order)

            float t_[6], mr_[6], bt[6];
            #pragma unroll
            for (int r = 0; r < 3; r++) {
                const int slot = (r == 0) ? s0r : (r == 1) ? s1r : s2r;
                const int R = c * 3 + slot;
                float4 v = *(const float4*)&Gs[R * GS_STR + 4 + pxl];
                float lft = __shfl_up_sync(0xffffffffu, v.w, 1);
                float rgt = __shfl_down_sync(0xffffffffu, v.x, 1);
                if (pg == 0) lft = Gs[R * GS_STR + 3 + pxl];
                if (pg == 7) rgt = Gs[R * GS_STR + 8 + pxl];
                float* a = (r == 0) ? t_ : (r == 1) ? mr_ : bt;
                a[0] = lft; a[1] = v.x; a[2] = v.y; a[3] = v.z; a[4] = v.w; a[5] = rgt;
            }

            float idv[4], sxv[4], syv[4];
            #pragma unroll
            for (int j = 0; j < 4; j++) {
                // sobel_x = [[1,0,1],[2,0,-2],[1,0,-1]]/8, sobel_y std (/8 in w1)
                float u  = t_[j] + t_[j+2];
                idv[j] = mr_[j+1];
                sxv[j] = u + 2.f*(mr_[j] - mr_[j+2]) + bt[j] - bt[j+2];
                syv[j] = u + 2.f*t_[j+1] - bt[j] - 2.f*bt[j+1] - bt[j+2];
            }

            half2 p0, p1;
            p0 = __floats2half2_rn(idv[0], idv[1]); p1 = __floats2half2_rn(idv[2], idv[3]);
            *(uint2*)&AsT[c * AT_STR + pxl]        = make_uint2(*(unsigned*)&p0, *(unsigned*)&p1);
            p0 = __floats2half2_rn(sxv[0], sxv[1]); p1 = __floats2half2_rn(sxv[2], sxv[3]);
            *(uint2*)&AsT[(16 + c) * AT_STR + pxl] = make_uint2(*(unsigned*)&p0, *(unsigned*)&p1);
            p0 = __floats2half2_rn(syv[0], syv[1]); p1 = __floats2half2_rn(syv[2], syv[3]);
            *(uint2*)&AsT[(32 + c) * AT_STR + pxl] = make_uint2(*(unsigned*)&p0, *(unsigned*)&p1);
        }
        __syncwarp();                              // own AsT columns visible to own ldmatrix

        __syncthreads();                           // BAR(1): all perception reads of s0r done

        // ---- stage NEXT iteration's new row (h+2) into freed slot s0r ----
        if (i + 1 < cnt && h < 255) {
            const int hn = h + 2;
            #pragma unroll
            for (int j = 0; j < 4; j++) {
                int idx  = j * THREADS + tid;        // 0..1023
                int c    = idx >> 6;
                int colq = idx & 63;
                float4 v = make_float4(0.f, 0.f, 0.f, 0.f);
                if (hn < 256)
                    v = *(const float4*)&grid[((((b*TC + c) << 8) + hn) << 8) + (colq << 2)];
                *(float4*)&Gs[(c*3 + s0r)*GS_STR + 4 + (colq << 2)] = v;
            }
        }

        // ---- GEMM1: [256 x 48] x w1^T[48 x 128], fp16 accum ----
        unsigned acc[2][16][2];
        #pragma unroll
        for (int s = 0; s < 2; s++)
            #pragma unroll
            for (int nt = 0; nt < 16; nt++) { acc[s][nt][0] = 0u; acc[s][nt][1] = 0u; }

        #pragma unroll
        for (int kt = 0; kt < 3; kt++) {
            unsigned a00, a01, a02, a03, a10, a11, a12, a13;
            ldm_x4_trans(a00, a01, a02, a03, a_b0 + kt * (16 * AT_STR * 2));
            ldm_x4_trans(a10, a11, a12, a13, a_b1 + kt * (16 * AT_STR * 2));
            #pragma unroll
            for (int ntp = 0; ntp < 8; ntp++) {
                unsigned b0, b1r, b2r, b3;
                ldm_x4(b0, b1r, b2r, b3,
                       b1_base + (uint32_t)(ntp * 16 * W1_STR * 2) + kt * 32);
                mma_f16acc(acc[0][2*ntp    ], a00, a01, a02, a03, b0,  b1r);
                mma_f16acc(acc[0][2*ntp + 1], a00, a01, a02, a03, b2r, b3);
                mma_f16acc(acc[1][2*ntp    ], a10, a11, a12, a13, b0,  b1r);
                mma_f16acc(acc[1][2*ntp + 1], a10, a11, a12, a13, b2r, b3);
            }
        }

        // bias + relu
        {
            const half2* B1p = g_b1h2 + tg;
            #pragma unroll
            for (int nt = 0; nt < 16; nt++) {
                half2 bb = B1p[4 * nt];
                unsigned bbu = *(unsigned*)&bb;
                #pragma unroll
                for (int s = 0; s < 2; s++) {
                    acc[s][nt][0] = hfma2_relu_bias(acc[s][nt][0], bbu);
                    acc[s][nt][1] = hfma2_relu_bias(acc[s][nt][1], bbu);
                }
            }
        }

        // ---- GEMM2: [32 x 128] x w2^T[128 x 16], fp32 accum ----
        float acc2[2][2][4];
        #pragma unroll
        for (int s = 0; s < 2; s++)
            #pragma unroll
            for (int nt = 0; nt < 2; nt++) {
                acc2[s][nt][0] = 0.f; acc2[s][nt][1] = 0.f;
                acc2[s][nt][2] = 0.f; acc2[s][nt][3] = 0.f;
            }
        #pragma unroll
        for (int kt = 0; kt < 8; kt++) {
            unsigned b0, b1r, b2r, b3;
            ldm_x4(b0, b1r, b2r, b3, b2_base + kt * 32);
            #pragma unroll
            for (int s = 0; s < 2; s++) {
                unsigned a0 = acc[s][2*kt][0],   a1 = acc[s][2*kt][1];
                unsigned a2 = acc[s][2*kt+1][0], a3 = acc[s][2*kt+1][1];
                mma_f32acc(acc2[s][0], a0, a1, a2, a3, b0,  b1r);
                mma_f32acc(acc2[s][1], a0, a1, a2, a3, b2r, b3);
            }
        }

        // ---- epilogue part 1: compute clipped outputs into Gout (smem) ----
        const float* nrow = noise + (((b << 8) + h) << 8);
        #pragma unroll
        for (int s = 0; s < 2; s++) {
            const int pix0 = m0 + 16*s + g;
            const int pix1 = pix0 + 8;
            const float mk0 = (nrow[pix0] < 0.5f) ? 1.f : 0.f;
            const float mk1 = (nrow[pix1] < 0.5f) ? 1.f : 0.f;
            #pragma unroll
            for (int nt = 0; nt < 2; nt++) {
                #pragma unroll
                for (int rr = 0; rr < 2; rr++) {
                    int   c   = (nt << 3) + 2*tg + rr;
                    float gc0 = Gs[(c*3 + s1r)*GS_STR + pix0 + 4];
                    float gc1 = Gs[(c*3 + s1r)*GS_STR + pix1 + 4];
                    float u0  = (acc2[s][nt][rr]     + bb_[nt][rr]) * mk0;
                    float u1  = (acc2[s][nt][2 + rr] + bb_[nt][rr]) * mk1;
                    Gout[c*GO_STR + pix0] = fminf(fmaxf(gc0 + u0, -2.f), 2.f);
                    Gout[c*GO_STR + pix1] = fminf(fmaxf(gc1 + u1, -2.f), 2.f);
                }
            }
        }
        __syncthreads();                           // BAR(2): Gout done, staged row done

        // ---- epilogue part 2: vectorized store ----
        const int out_base = ((b*TC) << 16) + (h << 8);
        #pragma unroll
        for (int j = 0; j < 4; j++) {
            int idx = j * THREADS + tid;           // 0..1023
            int c   = idx >> 6;
            int q4  = (idx & 63) << 2;
            float4 v = *(const float4*)&Gout[c*GO_STR + q4];
            *(float4*)&out[out_base + (c << 16) + q4] = v;
        }
        __syncthreads();                           // Gout/Gs stable before next iteration
    }
}

extern "C" void kernel_launch(void* const* d_in, const int* in_sizes, int n_in,
                              void* d_out, int out_size)
{
    const float* grid  = (const float*)d_in[0];
    const float* noise = (const float*)d_in[1];
    const float* w1    = (const float*)d_in[2];
    const float* b1    = (const float*)d_in[3];
    const float* w2    = (const float*)d_in[4];
    const float* b2    = (const float*)d_in[5];
    float* out = (float*)d_out;

    static bool attr_set = false;
    if (!attr_set) {
        cudaFuncSetAttribute(nca_step_kernel,
                             cudaFuncAttributeMaxDynamicSharedMemorySize, SMEM_BYTES);
        attr_set = true;
    }

    int nsm = 148;
    cudaDeviceGetAttribute(&nsm, cudaDevAttrMultiProcessorCount, 0);
    int ncta = nsm * 2;
    if (ncta > NROWT) ncta = NROWT;

    convert_weights_kernel<<<1, THREADS>>>(w1, b1, w2);
    nca_step_kernel<<<ncta, THREADS, SMEM_BYTES>>>(grid, noise, b2, out, ncta);
}

// round 14
// speedup vs baseline: 1.1160x; 1.1160x over previous
#include <cuda_runtime.h>
#include <cuda_fp16.h>
#include <cstdint>

#define TC      16
#define HID     128
#define PCH     48
#define THREADS 256
#define NROWT   8192                // row-tiles: 32 batches * 256 rows

#define GS_STR  264                 // floats per Gs row, interior at col 4 (pix 0..255)
#define AT_STR  264                 // halfs per AsT row
#define W1_STR  56
#define W2_STR  136

// smem: Gs float[16*3*264] | AsT half[48*264] | Wh1 half[128*56] | Wh2 half[16*136]
#define OFF_GS   0
#define OFF_AST  (16*3*GS_STR*4)                  // 50688
#define OFF_WH1  (OFF_AST + PCH*AT_STR*2)         // 76032
#define OFF_WH2  (OFF_WH1 + HID*W1_STR*2)         // 90368
#define SMEM_BYTES (OFF_WH2 + TC*W2_STR*2)        // 94720

// Pre-converted, pre-padded weights (k-permuted w1: k = 16*filter + channel).
// Sobel filter rows (f=1,2) are pre-scaled by 0.125 so the kernel skips the mul.
__device__ __align__(16) half  g_wh1p[HID * W1_STR];
__device__ __align__(16) half  g_wh2p[TC * W2_STR];
__device__ __align__(16) half2 g_b1h2[HID / 2];

__global__ void convert_weights_kernel(const float* __restrict__ w1,
                                       const float* __restrict__ b1,
                                       const float* __restrict__ w2)
{
    int t = threadIdx.x;
    for (int i = t; i < HID * W1_STR; i += THREADS) g_wh1p[i] = __float2half(0.f);
    for (int i = t; i < TC * W2_STR; i += THREADS) g_wh2p[i] = __float2half(0.f);
    __syncthreads();
    for (int i = t; i < HID * PCH; i += THREADS) {
        int o = i / PCH, p = i % PCH;
        int c = p / 3, f = p % 3;                  // src col p = 3c+f
        float scale = (f == 0) ? 1.f : 0.125f;     // fold sobel /8 into weights
        g_wh1p[o * W1_STR + f * 16 + c] = __float2half(w1[i] * scale);
    }
    for (int i = t; i < TC * HID; i += THREADS)
        g_wh2p[(i / HID) * W2_STR + (i % HID)] = __float2half(w2[i]);
    if (t < HID / 2)
        g_b1h2[t] = __floats2half2_rn(b1[2 * t], b1[2 * t + 1]);
}

__device__ __forceinline__ void mma_f16acc(unsigned* d,
    unsigned a0, unsigned a1, unsigned a2, unsigned a3,
    unsigned b0, unsigned b1)
{
    asm volatile(
        "mma.sync.aligned.m16n8k16.row.col.f16.f16.f16.f16 "
        "{%0,%1}, {%2,%3,%4,%5}, {%6,%7}, {%0,%1};\n"
        : "+r"(d[0]), "+r"(d[1])
        : "r"(a0), "r"(a1), "r"(a2), "r"(a3), "r"(b0), "r"(b1));
}

__device__ __forceinline__ void mma_f32acc(float* d,
    unsigned a0, unsigned a1, unsigned a2, unsigned a3,
    unsigned b0, unsigned b1)
{
    asm volatile(
        "mma.sync.aligned.m16n8k16.row.col.f32.f16.f16.f32 "
        "{%0,%1,%2,%3}, {%4,%5,%6,%7}, {%8,%9}, {%0,%1,%2,%3};\n"
        : "+f"(d[0]), "+f"(d[1]), "+f"(d[2]), "+f"(d[3])
        : "r"(a0), "r"(a1), "r"(a2), "r"(a3), "r"(b0), "r"(b1));
}

__device__ __forceinline__ void ldm_x4(unsigned& r0, unsigned& r1,
                                       unsigned& r2, unsigned& r3, uint32_t addr)
{
    asm volatile(
        "ldmatrix.sync.aligned.m8n8.x4.shared.b16 {%0,%1,%2,%3}, [%4];\n"
        : "=r"(r0), "=r"(r1), "=r"(r2), "=r"(r3) : "r"(addr));
}

__device__ __forceinline__ void ldm_x4_trans(unsigned& r0, unsigned& r1,
                                             unsigned& r2, unsigned& r3, uint32_t addr)
{
    asm volatile(
        "ldmatrix.sync.aligned.m8n8.x4.trans.shared.b16 {%0,%1,%2,%3}, [%4];\n"
        : "=r"(r0), "=r"(r1), "=r"(r2), "=r"(r3) : "r"(addr));
}

// relu(a + bias) in one instruction: fma.rn.relu with multiplier 1.0h x2
__device__ __forceinline__ unsigned hfma2_relu_bias(unsigned a, unsigned bias)
{
    unsigned d;
    const unsigned one2 = 0x3C003C00u;
    asm("fma.rn.relu.f16x2 %0, %1, %2, %3;\n" : "=r"(d) : "r"(a), "r"(one2), "r"(bias));
    return d;
}

__global__ __launch_bounds__(THREADS, 2)
void nca_step_kernel(const float* __restrict__ grid,
                     const float* __restrict__ noise,
                     const float* __restrict__ b2,
                     float* __restrict__ out,
                     int ncta)
{
    extern __shared__ __align__(128) char smem_raw[];
    float* Gs  = (float*)(smem_raw + OFF_GS);      // [16][3 slots][264], slot = row mod 3
    half*  AsT = (half*)(smem_raw + OFF_AST);      // [48][264] k-major
    half*  Wh1 = (half*)(smem_raw + OFF_WH1);      // [128][56]
    half*  Wh2 = (half*)(smem_raw + OFF_WH2);      // [16][136]

    const int tid = threadIdx.x;
    const int cta = blockIdx.x;

    // contiguous tile range for this CTA
    const int base  = NROWT / ncta;
    const int rem   = NROWT % ncta;
    const int start = cta * base + (cta < rem ? cta : rem);
    const int cnt   = base + (cta < rem ? 1 : 0);

    // ---- stage weights once per CTA (vector memcpy of pre-padded layouts) ----
    {
        const uint4* s1 = (const uint4*)g_wh1p;
        uint4*       d1 = (uint4*)Wh1;
        for (int i = tid; i < (HID*W1_STR)/8; i += THREADS) d1[i] = s1[i];
        const uint4* s2 = (const uint4*)g_wh2p;
        uint4*       d2 = (uint4*)Wh2;
        for (int i = tid; i < (TC*W2_STR)/8; i += THREADS) d2[i] = s2[i];
    }
    // static side-halo columns: always image-OOB -> zero once
    if (tid < 96) {
        int rowid = tid >> 1;
        int side  = tid & 1;
        int c     = rowid / 3;
        int r     = rowid - c * 3;
        Gs[(c*3 + r)*GS_STR + (side ? 260 : 3)] = 0.f;
    }

    // ---- per-thread constants ----
    const int lane = tid & 31;
    const int g    = lane >> 2;
    const int tg   = lane & 3;
    const int m0   = (tid >> 5) << 5;              // 32 pixels per warp

    const uint32_t ast_sm = (uint32_t)__cvta_generic_to_shared(AsT);
    const uint32_t a_row  = (lane & 7) + ((lane >> 4) << 3);
    const uint32_t a_b0   = ast_sm + (uint32_t)((a_row * AT_STR + m0      + (lane & 8)) * 2);
    const uint32_t a_b1   = ast_sm + (uint32_t)((a_row * AT_STR + m0 + 16 + (lane & 8)) * 2);
    const uint32_t brow = (lane & 7) + ((lane >> 4) << 3);
    const uint32_t bkof = (lane & 8);
    const uint32_t b1_base = (uint32_t)__cvta_generic_to_shared(Wh1) + (brow * W1_STR + bkof) * 2;
    const uint32_t b2_base = (uint32_t)__cvta_generic_to_shared(Wh2) + (brow * W2_STR + bkof) * 2;

    // epilogue channel biases are per-thread constants: hoist
    float bb_[2][2];
    #pragma unroll
    for (int nt = 0; nt < 2; nt++)
        #pragma unroll
        for (int rr = 0; rr < 2; rr++)
            bb_[nt][rr] = b2[(nt << 3) + 2*tg + rr];

    __syncthreads();

    for (int i = 0; i < cnt; i++) {
        const int tile = start + i;                // row-tile: b*256 + h (consecutive)
        const int b    = tile >> 8;
        const int h    = tile & 255;

        // uniform slot indices: row r lives in slot r mod 3
        const int s1r = (unsigned)h % 3u;                       // row h
        const int s2r = (s1r + 1 == 3) ? 0 : s1r + 1;           // row h+1
        const int s0r = (s1r == 0) ? 2 : s1r - 1;               // row h-1

        if (i == 0 || h == 0) {
            // full restage: rows h-1, h, h+1 into their slots
            #pragma unroll
            for (int j = 0; j < 12; j++) {
                int idx   = j * THREADS + tid;       // 0..3071
                int rowid = idx >> 6;                // 0..47
                int c     = rowid / 3;
                int rr    = rowid - c * 3;           // 0..2
                int colq  = idx & 63;
                int r_img = h + rr - 1;
                int slot  = (rr == 0) ? s0r : (rr == 1) ? s1r : s2r;
                float4 v  = make_float4(0.f, 0.f, 0.f, 0.f);
                if ((unsigned)r_img < 256u)
                    v = *(const float4*)&grid[((((b*TC + c) << 8) + r_img) << 8) + (colq << 2)];
                *(float4*)&Gs[(c*3 + slot)*GS_STR + 4 + (colq << 2)] = v;
            }
        } else {
            // steady state: only row h+1 is new (rows h-1, h already resident)
            const int hn = h + 1;
            #pragma unroll
            for (int j = 0; j < 4; j++) {
                int idx  = j * THREADS + tid;        // 0..1023
                int c    = idx >> 6;
                int colq = idx & 63;
                float4 v = make_float4(0.f, 0.f, 0.f, 0.f);
                if (hn < 256)
                    v = *(const float4*)&grid[((((b*TC + c) << 8) + hn) << 8) + (colq << 2)];
                *(float4*)&Gs[(c*3 + s2r)*GS_STR + 4 + (colq << 2)] = v;
            }
        }

        // ---- HOISTED: noise loads + masks (DRAM/L2 latency hidden under
        //      perception + GEMM instead of exposed at epilogue) ----
        const float* nrow = noise + (((b << 8) + h) << 8);
        float mk_[2][2];
        #pragma unroll
        for (int s = 0; s < 2; s++) {
            mk_[s][0] = (nrow[m0 + 16*s + g]     < 0.5f) ? 1.f : 0.f;
            mk_[s][1] = (nrow[m0 + 16*s + g + 8] < 0.5f) ? 1.f : 0.f;
        }

        __syncthreads();

        // ---- perception: 4 px x 1 ch per thread (sobel /8 folded into w1) ----
        #pragma unroll
        for (int it = 0; it < 4; it++) {
            int idx  = it * THREADS + tid;       // 0..1023
            int c    = idx >> 6;                 // channel 0..15
            int grp  = idx & 63;                 // lanes consecutive within warp
            int pix0 = grp << 2;

            float t_[6], mr_[6], bt[6];
            #pragma unroll
            for (int r = 0; r < 3; r++) {
                const int slot = (r == 0) ? s0r : (r == 1) ? s1r : s2r;
                const int R = c * 3 + slot;
                float4 v = *(const float4*)&Gs[R * GS_STR + 4 + pix0];
                float lft = __shfl_up_sync(0xffffffffu, v.w, 1);
                float rgt = __shfl_down_sync(0xffffffffu, v.x, 1);
                if (lane == 0)  lft = Gs[R * GS_STR + 3 + pix0];
                if (lane == 31) rgt = Gs[R * GS_STR + 8 + pix0];
                float* a = (r == 0) ? t_ : (r == 1) ? mr_ : bt;
                a[0] = lft; a[1] = v.x; a[2] = v.y; a[3] = v.z; a[4] = v.w; a[5] = rgt;
            }

            float idv[4], sxv[4], syv[4];
            #pragma unroll
            for (int j = 0; j < 4; j++) {
                // reference sobel_x = [[1,0,1],[2,0,-2],[1,0,-1]]/8 (scale in w1)
                // reference sobel_y = [[1,2,1],[0,0,0],[-1,-2,-1]]/8 (scale in w1)
                float u  = t_[j] + t_[j+2];                      // shared by sx & sy
                idv[j] = mr_[j+1];
                sxv[j] = u + 2.f*(mr_[j] - mr_[j+2]) + bt[j] - bt[j+2];
                syv[j] = u + 2.f*t_[j+1] - bt[j] - 2.f*bt[j+1] - bt[j+2];
            }

            half2 p0, p1;
            p0 = __floats2half2_rn(idv[0], idv[1]); p1 = __floats2half2_rn(idv[2], idv[3]);
            *(uint2*)&AsT[c * AT_STR + pix0]        = make_uint2(*(unsigned*)&p0, *(unsigned*)&p1);
            p0 = __floats2half2_rn(sxv[0], sxv[1]); p1 = __floats2half2_rn(sxv[2], sxv[3]);
            *(uint2*)&AsT[(16 + c) * AT_STR + pix0] = make_uint2(*(unsigned*)&p0, *(unsigned*)&p1);
            p0 = __floats2half2_rn(syv[0], syv[1]); p1 = __floats2half2_rn(syv[2], syv[3]);
            *(uint2*)&AsT[(32 + c) * AT_STR + pix0] = make_uint2(*(unsigned*)&p0, *(unsigned*)&p1);
        }
        __syncthreads();

        // ---- GEMM1: [256 x 48] x w1^T[48 x 128], fp16 accum, 2 sub-tiles/warp ----
        unsigned acc[2][16][2];
        #pragma unroll
        for (int s = 0; s < 2; s++)
            #pragma unroll
            for (int nt = 0; nt < 16; nt++) { acc[s][nt][0] = 0u; acc[s][nt][1] = 0u; }

        #pragma unroll
        for (int kt = 0; kt < 3; kt++) {
            unsigned a00, a01, a02, a03, a10, a11, a12, a13;
            ldm_x4_trans(a00, a01, a02, a03, a_b0 + kt * (16 * AT_STR * 2));
            ldm_x4_trans(a10, a11, a12, a13, a_b1 + kt * (16 * AT_STR * 2));
            #pragma unroll
            for (int ntp = 0; ntp < 8; ntp++) {
                unsigned b0, b1r, b2r, b3;
                ldm_x4(b0, b1r, b2r, b3,
                       b1_base + (uint32_t)(ntp * 16 * W1_STR * 2) + kt * 32);
                mma_f16acc(acc[0][2*ntp    ], a00, a01, a02, a03, b0,  b1r);
                mma_f16acc(acc[0][2*ntp + 1], a00, a01, a02, a03, b2r, b3);
                mma_f16acc(acc[1][2*ntp    ], a10, a11, a12, a13, b0,  b1r);
                mma_f16acc(acc[1][2*ntp + 1], a10, a11, a12, a13, b2r, b3);
            }
        }

        // bias + relu in one fma.rn.relu.f16x2 each -> acc becomes GEMM2 A frags
        {
            const half2* B1p = g_b1h2 + tg;
            #pragma unroll
            for (int nt = 0; nt < 16; nt++) {
                half2 bb = B1p[4 * nt];
                unsigned bbu = *(unsigned*)&bb;
                #pragma unroll
                for (int s = 0; s < 2; s++) {
                    acc[s][nt][0] = hfma2_relu_bias(acc[s][nt][0], bbu);
                    acc[s][nt][1] = hfma2_relu_bias(acc[s][nt][1], bbu);
                }
            }
        }

        // ---- GEMM2: [32 x 128] x w2^T[128 x 16], fp32 accum ----
        float acc2[2][2][4];
        #pragma unroll
        for (int s = 0; s < 2; s++)
            #pragma unroll
            for (int nt = 0; nt < 2; nt++) {
                acc2[s][nt][0] = 0.f; acc2[s][nt][1] = 0.f;
                acc2[s][nt][2] = 0.f; acc2[s][nt][3] = 0.f;
            }
        #pragma unroll
        for (int kt = 0; kt < 8; kt++) {
            unsigned b0, b1r, b2r, b3;
            ldm_x4(b0, b1r, b2r, b3, b2_base + kt * 32);
            #pragma unroll
            for (int s = 0; s < 2; s++) {
                unsigned a0 = acc[s][2*kt][0],   a1 = acc[s][2*kt][1];
                unsigned a2 = acc[s][2*kt+1][0], a3 = acc[s][2*kt+1][1];
                mma_f32acc(acc2[s][0], a0, a1, a2, a3, b0,  b1r);
                mma_f32acc(acc2[s][1], a0, a1, a2, a3, b2r, b3);
            }
        }

        // ---- epilogue (residual from slot s1r = row h; masks precomputed) ----
        const int out_base = ((b*TC) << 16) + (h << 8);

        #pragma unroll
        for (int s = 0; s < 2; s++) {
            const int pix0 = m0 + 16*s + g;
            const int pix1 = pix0 + 8;
            const float mk0 = mk_[s][0];
            const float mk1 = mk_[s][1];
            #pragma unroll
            for (int nt = 0; nt < 2; nt++) {
                #pragma unroll
                for (int rr = 0; rr < 2; rr++) {
                    int   c   = (nt << 3) + 2*tg + rr;
                    float gc0 = Gs[(c*3 + s1r)*GS_STR + pix0 + 4];
                    float gc1 = Gs[(c*3 + s1r)*GS_STR + pix1 + 4];
                    float u0  = (acc2[s][nt][rr]     + bb_[nt][rr]) * mk0;
                    float u1  = (acc2[s][nt][2 + rr] + bb_[nt][rr]) * mk1;
                    out[out_base + (c << 16) + pix0] = fminf(fmaxf(gc0 + u0, -2.f), 2.f);
                    out[out_base + (c << 16) + pix1] = fminf(fmaxf(gc1 + u1, -2.f), 2.f);
                }
            }
        }
        // trailing barrier only needed before a FULL restage (next h == 0),
        // which overwrites slot s1r that this epilogue reads. Steady-state
        // staging writes slot s0r, whose readers (perception) are already
        // fenced by this iteration's mid barriers.
        if (h == 255) __syncthreads();
    }
}

extern "C" void kernel_launch(void* const* d_in, const int* in_sizes, int n_in,
                              void* d_out, int out_size)
{
    const float* grid  = (const float*)d_in[0];
    const float* noise = (const float*)d_in[1];
    const float* w1    = (const float*)d_in[2];
    const float* b1    = (const float*)d_in[3];
    const float* w2    = (const float*)d_in[4];
    const float* b2    = (const float*)d_in[5];
    float* out = (float*)d_out;

    static bool attr_set = false;
    if (!attr_set) {
        cudaFuncSetAttribute(nca_step_kernel,
                             cudaFuncAttributeMaxDynamicSharedMemorySize, SMEM_BYTES);
        attr_set = true;
    }

    int nsm = 148;
    cudaDeviceGetAttribute(&nsm, cudaDevAttrMultiProcessorCount, 0);
    int ncta = nsm * 2;
    if (ncta > NROWT) ncta = NROWT;

    convert_weights_kernel<<<1, THREADS>>>(w1, b1, w2);
    nca_step_kernel<<<ncta, THREADS, SMEM_BYTES>>>(grid, noise, b2, out, ncta);
}